// round 12
// baseline (speedup 1.0000x reference)
#include <cuda_runtime.h>
#include <cstddef>

#define N_NODES 100000
#define N_EDGES 1600000
#define IN_CH   128
#define HEADS   4
#define OUT_CH  32
#define F_TOT   128   // HEADS*OUT_CH
#define MAX_SLOTS 256

// Scratch (static __device__ allocation; runtime alloc forbidden)
__device__ float    g_proj[(size_t)N_NODES * F_TOT];   // 51.2 MB
__device__ float    g_norm[(size_t)N_NODES * HEADS];   // 1.6 MB
__device__ unsigned g_slot[HEADS * MAX_SLOTS];         // hashed per-head max slots
__device__ float    g_hmax[HEADS];                     // final per-head max

// monotone float->uint map (order-preserving); inverse for readback
__device__ __forceinline__ unsigned fmap(float f) {
    unsigned u = __float_as_uint(f);
    return (u & 0x80000000u) ? ~u : (u | 0x80000000u);
}
__device__ __forceinline__ float funmap(unsigned u) {
    return __uint_as_float((u & 0x80000000u) ? (u & 0x7FFFFFFFu) : ~u);
}

// fast tanh: 2 MUFU + few FMA; rel err ~1e-6 (validated: pipeline rel_err 3.7e-7)
__device__ __forceinline__ float fast_tanh(float x) {
    float ax = fabsf(x);
    float e  = __expf(2.0f * ax);             // inf for large ax -> r = 1
    float r  = 1.0f - __fdividef(2.0f, e + 1.0f);
    return copysignf(r, x);
}

// ---------------------------------------------------------------------------
// GEMM v3: 128x128 tile / 256 threads, 8x8 microtile, register-buffered
// k-pipeline: next tile's global loads issued before the compute loop so
// their ~600cyc latency overlaps 1024 FFMAs. Row pad 132 (16B-aligned).
// B loader: thread t -> W row kk+ty, cols [8tx, 8tx+8).
// ---------------------------------------------------------------------------
__global__ __launch_bounds__(256) void gemm_kernel(const float* __restrict__ x,
                                                   const float* __restrict__ Wm) {
    __shared__ float xs_t[16][132];    // [k][row], pad 132 (16B-aligned rows)
    __shared__ float ws[16][128];      // [k][col]
    const int t  = threadIdx.x;
    const int tx = t & 15;             // col group
    const int ty = t >> 4;             // row group
    const int rowBase = blockIdx.x * 128;

    float acc[8][8];
#pragma unroll
    for (int i = 0; i < 8; i++)
#pragma unroll
        for (int j = 0; j < 8; j++) acc[i][j] = 0.f;

    // A loader: thread t -> row lr = t>>1 (0..127), k-half lk8 = (t&1)*8
    const int lr  = t >> 1;
    const int lk8 = (t & 1) * 8;
    int gr = rowBase + lr;
    if (gr >= N_NODES) gr = N_NODES - 1;   // clamp (dup loads OK, stores guarded)
    const float* xrow = x + (size_t)gr * IN_CH + lk8;
    const float* wrow = Wm + (size_t)ty * F_TOT + tx * 8;

    // prefetch tile 0
    float4 av0 = *(const float4*)(xrow);
    float4 av1 = *(const float4*)(xrow + 4);
    float4 bv0 = *(const float4*)(wrow);
    float4 bv1 = *(const float4*)(wrow + 4);

#pragma unroll
    for (int s = 0; s < IN_CH / 16; s++) {
        // store current tile regs -> smem
        xs_t[lk8 + 0][lr] = av0.x; xs_t[lk8 + 1][lr] = av0.y;
        xs_t[lk8 + 2][lr] = av0.z; xs_t[lk8 + 3][lr] = av0.w;
        xs_t[lk8 + 4][lr] = av1.x; xs_t[lk8 + 5][lr] = av1.y;
        xs_t[lk8 + 6][lr] = av1.z; xs_t[lk8 + 7][lr] = av1.w;
        *(float4*)&ws[ty][tx * 8]     = bv0;
        *(float4*)&ws[ty][tx * 8 + 4] = bv1;
        __syncthreads();

        // issue next tile's global loads (overlap with compute below)
        if (s < IN_CH / 16 - 1) {
            const int kk = (s + 1) * 16;
            av0 = *(const float4*)(xrow + kk);
            av1 = *(const float4*)(xrow + kk + 4);
            bv0 = *(const float4*)(wrow + (size_t)kk * F_TOT);
            bv1 = *(const float4*)(wrow + (size_t)kk * F_TOT + 4);
        }

#pragma unroll
        for (int k = 0; k < 16; k++) {
            float4 a0 = *(float4*)&xs_t[k][ty * 8];
            float4 a1 = *(float4*)&xs_t[k][ty * 8 + 4];
            float4 b0 = *(float4*)&ws[k][tx * 8];
            float4 b1 = *(float4*)&ws[k][tx * 8 + 4];
            float a[8] = {a0.x, a0.y, a0.z, a0.w, a1.x, a1.y, a1.z, a1.w};
            float b[8] = {b0.x, b0.y, b0.z, b0.w, b1.x, b1.y, b1.z, b1.w};
#pragma unroll
            for (int i = 0; i < 8; i++)
#pragma unroll
                for (int j = 0; j < 8; j++)
                    acc[i][j] += a[i] * b[j];
        }
        __syncthreads();
    }

#pragma unroll
    for (int i = 0; i < 8; i++) {
        int r = rowBase + ty * 8 + i;
        if (r < N_NODES) {
            *(float4*)(g_proj + (size_t)r * F_TOT + tx * 8) =
                make_float4(acc[i][0], acc[i][1], acc[i][2], acc[i][3]);
            *(float4*)(g_proj + (size_t)r * F_TOT + tx * 8 + 4) =
                make_float4(acc[i][4], acc[i][5], acc[i][6], acc[i][7]);
        }
    }
}

// ---------------------------------------------------------------------------
// Edge kernel: one warp per edge, 8 edges/block, 200000 blocks exactly.
// Gathers use __ldcg (L2-only): random access over 51.2MB has ~no L1 reuse,
// so L1 allocation is pure overhead. Rest identical to known-good R6.
// ---------------------------------------------------------------------------
__global__ __launch_bounds__(256) void edge_kernel(const int* __restrict__ ei,
                                                   const float* __restrict__ att,
                                                   float* __restrict__ out) {
    const int warpInBlk = threadIdx.x >> 5;
    const int lane      = threadIdx.x & 31;
    const int edge      = blockIdx.x * 8 + warpInBlk;

    __shared__ float smax[8][HEADS];

    const int row = __ldg(ei + edge);
    const int col = __ldg(ei + N_EDGES + edge);

    const float4 s4 = __ldcg((const float4*)(g_proj + (size_t)row * F_TOT + lane * 4));
    const float4 d4 = __ldcg((const float4*)(g_proj + (size_t)col * F_TOT + lane * 4));
    const float4 a4 = *(const float4*)(att + lane * 4);

    float p = fast_tanh(s4.x + d4.x) * a4.x
            + fast_tanh(s4.y + d4.y) * a4.y
            + fast_tanh(s4.z + d4.z) * a4.z
            + fast_tanh(s4.w + d4.w) * a4.w;

    // reduce within each 8-lane head group (all lanes get the sum)
    p += __shfl_xor_sync(0xffffffffu, p, 4);
    p += __shfl_xor_sync(0xffffffffu, p, 2);
    p += __shfl_xor_sync(0xffffffffu, p, 1);

    if ((lane & 7) == 0) smax[warpInBlk][lane >> 3] = p;

    const float w = __expf(p);

    float* op = out + (size_t)col * F_TOT + lane * 4;
    asm volatile("red.global.add.v4.f32 [%0], {%1,%2,%3,%4};"
                 :: "l"(op), "f"(s4.x * w), "f"(s4.y * w),
                    "f"(s4.z * w), "f"(s4.w * w)
                 : "memory");

    if ((lane & 7) == 0)
        atomicAdd(g_norm + (size_t)col * HEADS + (lane >> 3), w);

    __syncthreads();
    if (threadIdx.x < HEADS) {
        float m = smax[0][threadIdx.x];
#pragma unroll
        for (int wb = 1; wb < 8; wb++) m = fmaxf(m, smax[wb][threadIdx.x]);
        atomicMax(&g_slot[threadIdx.x * MAX_SLOTS + (blockIdx.x & (MAX_SLOTS - 1))],
                  fmap(m));
    }
}

// ---------------------------------------------------------------------------
// Reduce hashed max slots -> g_hmax[h]
// ---------------------------------------------------------------------------
__global__ __launch_bounds__(256) void maxreduce_kernel() {
    __shared__ unsigned sm[256];
    const int t = threadIdx.x;
    for (int h = 0; h < HEADS; h++) {
        sm[t] = g_slot[h * MAX_SLOTS + t];
        __syncthreads();
        for (int s = 128; s > 0; s >>= 1) {
            if (t < s) sm[t] = max(sm[t], sm[t + s]);
            __syncthreads();
        }
        if (t == 0) g_hmax[h] = funmap(sm[0]);
        __syncthreads();
    }
}

// ---------------------------------------------------------------------------
// Finalize: exact reference semantics including the 1e-12 clamp:
//   scale = exp(-max_h); out = out_acc*scale / max(norm_acc*scale, 1e-12)
// ---------------------------------------------------------------------------
__global__ __launch_bounds__(256) void finalize_kernel(float* __restrict__ out) {
    size_t i4 = (size_t)blockIdx.x * blockDim.x + threadIdx.x;
    if (i4 >= (size_t)N_NODES * (F_TOT / 4)) return;
    int n = (int)(i4 >> 5);
    int q = (int)(i4 & 31);
    int h = q >> 3;
    float scale = __expf(-g_hmax[h]);
    float nr    = g_norm[(size_t)n * HEADS + h] * scale;
    float inv   = scale / fmaxf(nr, 1e-12f);
    float4 v = *(float4*)(out + i4 * 4);
    v.x *= inv; v.y *= inv; v.z *= inv; v.w *= inv;
    *(float4*)(out + i4 * 4) = v;
}

// ---------------------------------------------------------------------------
extern "C" void kernel_launch(void* const* d_in, const int* in_sizes, int n_in,
                              void* d_out, int out_size) {
    const float* x   = (const float*)d_in[0];
    const int*   ei  = (const int*)d_in[1];    // int32 edge_index [2, E]
    const float* Wm  = (const float*)d_in[2];
    const float* att = (const float*)d_in[3];
    float*       out = (float*)d_out;

    void* normPtr = nullptr;
    void* slotPtr = nullptr;
    cudaGetSymbolAddress(&normPtr, g_norm);
    cudaGetSymbolAddress(&slotPtr, g_slot);

    cudaMemsetAsync(out, 0, (size_t)N_NODES * F_TOT * sizeof(float));
    cudaMemsetAsync(normPtr, 0, (size_t)N_NODES * HEADS * sizeof(float));
    cudaMemsetAsync(slotPtr, 0, HEADS * MAX_SLOTS * sizeof(unsigned));

    gemm_kernel<<<(N_NODES + 127) / 128, 256>>>(x, Wm);

    edge_kernel<<<N_EDGES / 8, 256>>>(ei, att, out);   // 200000 blocks exactly

    maxreduce_kernel<<<1, 256>>>();

    const long long finElems = (long long)N_NODES * (F_TOT / 4);
    finalize_kernel<<<(unsigned)((finElems + 255) / 256), 256>>>(out);
}

// round 13
// speedup vs baseline: 1.0129x; 1.0129x over previous
#include <cuda_runtime.h>
#include <cstddef>

#define N_NODES 100000
#define N_EDGES 1600000
#define IN_CH   128
#define HEADS   4
#define OUT_CH  32
#define F_TOT   128   // HEADS*OUT_CH
#define MAX_SLOTS 256

// Scratch (static __device__ allocation; runtime alloc forbidden)
__device__ float    g_proj[(size_t)N_NODES * F_TOT];   // 51.2 MB
__device__ float    g_norm[(size_t)N_NODES * HEADS];   // 1.6 MB
__device__ unsigned g_slot[HEADS * MAX_SLOTS];         // hashed per-head max slots
__device__ float    g_hmax[HEADS];                     // final per-head max

// monotone float->uint map (order-preserving); inverse for readback
__device__ __forceinline__ unsigned fmap(float f) {
    unsigned u = __float_as_uint(f);
    return (u & 0x80000000u) ? ~u : (u | 0x80000000u);
}
__device__ __forceinline__ float funmap(unsigned u) {
    return __uint_as_float((u & 0x80000000u) ? (u & 0x7FFFFFFFu) : ~u);
}

// fast tanh: 2 MUFU + few FMA; rel err ~1e-6 (validated: pipeline rel_err 3.7e-7)
__device__ __forceinline__ float fast_tanh(float x) {
    float ax = fabsf(x);
    float e  = __expf(2.0f * ax);             // inf for large ax -> r = 1
    float r  = 1.0f - __fdividef(2.0f, e + 1.0f);
    return copysignf(r, x);
}

// ---------------------------------------------------------------------------
// GEMM v2b (exact R11 known-good): 128x128 tile / 256 threads, 8x8 microtile.
// Row pad 132 floats (16B-aligned rows). 64 FFMA + 4 LDS.128 per k-step.
// ---------------------------------------------------------------------------
__global__ __launch_bounds__(256) void gemm_kernel(const float* __restrict__ x,
                                                   const float* __restrict__ Wm) {
    __shared__ float xs_t[16][132];    // [k][row], pad 132 (16B-aligned rows)
    __shared__ float ws[16][128];      // [k][col]
    const int t  = threadIdx.x;
    const int tx = t & 15;             // col group
    const int ty = t >> 4;             // row group
    const int rowBase = blockIdx.x * 128;

    float acc[8][8];
#pragma unroll
    for (int i = 0; i < 8; i++)
#pragma unroll
        for (int j = 0; j < 8; j++) acc[i][j] = 0.f;

    const int lr  = t >> 1;
    const int lk8 = (t & 1) * 8;
    int gr = rowBase + lr;
    if (gr >= N_NODES) gr = N_NODES - 1;   // clamp (dup loads OK, stores guarded)

    for (int kk = 0; kk < IN_CH; kk += 16) {
        float4 v0 = *(const float4*)(x + (size_t)gr * IN_CH + kk + lk8);
        float4 v1 = *(const float4*)(x + (size_t)gr * IN_CH + kk + lk8 + 4);
        xs_t[lk8 + 0][lr] = v0.x; xs_t[lk8 + 1][lr] = v0.y;
        xs_t[lk8 + 2][lr] = v0.z; xs_t[lk8 + 3][lr] = v0.w;
        xs_t[lk8 + 4][lr] = v1.x; xs_t[lk8 + 5][lr] = v1.y;
        xs_t[lk8 + 6][lr] = v1.z; xs_t[lk8 + 7][lr] = v1.w;
#pragma unroll
        for (int rep = 0; rep < 2; rep++) {
            int idx = t * 2 + rep;            // 0..511
            int k   = idx >> 5;               // 0..15
            int c4  = (idx & 31) * 4;         // 0..124
            *(float4*)&ws[k][c4] =
                *(const float4*)(Wm + (size_t)(kk + k) * F_TOT + c4);
        }
        __syncthreads();
#pragma unroll
        for (int k = 0; k < 16; k++) {
            float4 a0 = *(float4*)&xs_t[k][ty * 8];
            float4 a1 = *(float4*)&xs_t[k][ty * 8 + 4];
            float4 b0 = *(float4*)&ws[k][tx * 8];
            float4 b1 = *(float4*)&ws[k][tx * 8 + 4];
            float a[8] = {a0.x, a0.y, a0.z, a0.w, a1.x, a1.y, a1.z, a1.w};
            float b[8] = {b0.x, b0.y, b0.z, b0.w, b1.x, b1.y, b1.z, b1.w};
#pragma unroll
            for (int i = 0; i < 8; i++)
#pragma unroll
                for (int j = 0; j < 8; j++)
                    acc[i][j] += a[i] * b[j];
        }
        __syncthreads();
    }

#pragma unroll
    for (int i = 0; i < 8; i++) {
        int r = rowBase + ty * 8 + i;
        if (r < N_NODES) {
            *(float4*)(g_proj + (size_t)r * F_TOT + tx * 8) =
                make_float4(acc[i][0], acc[i][1], acc[i][2], acc[i][3]);
            *(float4*)(g_proj + (size_t)r * F_TOT + tx * 8 + 4) =
                make_float4(acc[i][4], acc[i][5], acc[i][6], acc[i][7]);
        }
    }
}

// ---------------------------------------------------------------------------
// Edge kernel v2: 2 edges per warp, 16 lanes per edge, 8 channels per lane.
// half = lane>>4 selects the edge; sub = lane&15; head = sub>>2 (4-lane
// groups, xor-1/2-closed). Halves warp count and exp-MUFU instrs; shfl steps
// per edge-pair: 2 (was 6). Plain loads (L1 allowed - ldcg regressed in R12).
// 16 edges/block, E/16 = 100000 blocks exactly.
// ---------------------------------------------------------------------------
__global__ __launch_bounds__(256) void edge_kernel(const int* __restrict__ ei,
                                                   const float* __restrict__ att,
                                                   float* __restrict__ out) {
    const int warpInBlk = threadIdx.x >> 5;
    const int lane      = threadIdx.x & 31;
    const int half      = lane >> 4;          // which edge in the pair
    const int sub       = lane & 15;          // lane within edge
    const int edge      = blockIdx.x * 16 + warpInBlk * 2 + half;

    __shared__ float smax[16][HEADS];

    const int row = __ldg(ei + edge);
    const int col = __ldg(ei + N_EDGES + edge);

    const float* srow = g_proj + (size_t)row * F_TOT + sub * 8;
    const float* drow = g_proj + (size_t)col * F_TOT + sub * 8;
    const float4 sA = *(const float4*)(srow);
    const float4 sB = *(const float4*)(srow + 4);
    const float4 dA = *(const float4*)(drow);
    const float4 dB = *(const float4*)(drow + 4);
    const float4 aA = *(const float4*)(att + sub * 8);
    const float4 aB = *(const float4*)(att + sub * 8 + 4);

    float p = fast_tanh(sA.x + dA.x) * aA.x
            + fast_tanh(sA.y + dA.y) * aA.y
            + fast_tanh(sA.z + dA.z) * aA.z
            + fast_tanh(sA.w + dA.w) * aA.w
            + fast_tanh(sB.x + dB.x) * aB.x
            + fast_tanh(sB.y + dB.y) * aB.y
            + fast_tanh(sB.z + dB.z) * aB.z
            + fast_tanh(sB.w + dB.w) * aB.w;

    // reduce within each aligned 4-lane head group
    p += __shfl_xor_sync(0xffffffffu, p, 2);
    p += __shfl_xor_sync(0xffffffffu, p, 1);

    const int head = sub >> 2;
    if ((sub & 3) == 0) smax[warpInBlk * 2 + half][head] = p;

    const float w = __expf(p);

    float* op = out + (size_t)col * F_TOT + sub * 8;
    asm volatile("red.global.add.v4.f32 [%0], {%1,%2,%3,%4};"
                 :: "l"(op), "f"(sA.x * w), "f"(sA.y * w),
                    "f"(sA.z * w), "f"(sA.w * w)
                 : "memory");
    asm volatile("red.global.add.v4.f32 [%0], {%1,%2,%3,%4};"
                 :: "l"(op + 4), "f"(sB.x * w), "f"(sB.y * w),
                    "f"(sB.z * w), "f"(sB.w * w)
                 : "memory");

    if ((sub & 3) == 0)
        atomicAdd(g_norm + (size_t)col * HEADS + head, w);

    __syncthreads();
    if (threadIdx.x < HEADS) {
        float m = smax[0][threadIdx.x];
#pragma unroll
        for (int wb = 1; wb < 16; wb++) m = fmaxf(m, smax[wb][threadIdx.x]);
        atomicMax(&g_slot[threadIdx.x * MAX_SLOTS + (blockIdx.x & (MAX_SLOTS - 1))],
                  fmap(m));
    }
}

// ---------------------------------------------------------------------------
// Reduce hashed max slots -> g_hmax[h]
// ---------------------------------------------------------------------------
__global__ __launch_bounds__(256) void maxreduce_kernel() {
    __shared__ unsigned sm[256];
    const int t = threadIdx.x;
    for (int h = 0; h < HEADS; h++) {
        sm[t] = g_slot[h * MAX_SLOTS + t];
        __syncthreads();
        for (int s = 128; s > 0; s >>= 1) {
            if (t < s) sm[t] = max(sm[t], sm[t + s]);
            __syncthreads();
        }
        if (t == 0) g_hmax[h] = funmap(sm[0]);
        __syncthreads();
    }
}

// ---------------------------------------------------------------------------
// Finalize: exact reference semantics including the 1e-12 clamp:
//   scale = exp(-max_h); out = out_acc*scale / max(norm_acc*scale, 1e-12)
// ---------------------------------------------------------------------------
__global__ __launch_bounds__(256) void finalize_kernel(float* __restrict__ out) {
    size_t i4 = (size_t)blockIdx.x * blockDim.x + threadIdx.x;
    if (i4 >= (size_t)N_NODES * (F_TOT / 4)) return;
    int n = (int)(i4 >> 5);
    int q = (int)(i4 & 31);
    int h = q >> 3;
    float scale = __expf(-g_hmax[h]);
    float nr    = g_norm[(size_t)n * HEADS + h] * scale;
    float inv   = scale / fmaxf(nr, 1e-12f);
    float4 v = *(float4*)(out + i4 * 4);
    v.x *= inv; v.y *= inv; v.z *= inv; v.w *= inv;
    *(float4*)(out + i4 * 4) = v;
}

// ---------------------------------------------------------------------------
extern "C" void kernel_launch(void* const* d_in, const int* in_sizes, int n_in,
                              void* d_out, int out_size) {
    const float* x   = (const float*)d_in[0];
    const int*   ei  = (const int*)d_in[1];    // int32 edge_index [2, E]
    const float* Wm  = (const float*)d_in[2];
    const float* att = (const float*)d_in[3];
    float*       out = (float*)d_out;

    void* normPtr = nullptr;
    void* slotPtr = nullptr;
    cudaGetSymbolAddress(&normPtr, g_norm);
    cudaGetSymbolAddress(&slotPtr, g_slot);

    cudaMemsetAsync(out, 0, (size_t)N_NODES * F_TOT * sizeof(float));
    cudaMemsetAsync(normPtr, 0, (size_t)N_NODES * HEADS * sizeof(float));
    cudaMemsetAsync(slotPtr, 0, HEADS * MAX_SLOTS * sizeof(unsigned));

    gemm_kernel<<<(N_NODES + 127) / 128, 256>>>(x, Wm);

    edge_kernel<<<N_EDGES / 16, 256>>>(ei, att, out);  // 100000 blocks exactly

    maxreduce_kernel<<<1, 256>>>();

    const long long finElems = (long long)N_NODES * (F_TOT / 4);
    finalize_kernel<<<(unsigned)((finElems + 255) / 256), 256>>>(out);
}

// round 14
// speedup vs baseline: 1.0762x; 1.0626x over previous
#include <cuda_runtime.h>
#include <cstddef>
#include <cstdint>

#define N_NODES 100000
#define N_EDGES 1600000
#define IN_CH   128
#define HEADS   4
#define OUT_CH  32
#define F_TOT   128   // HEADS*OUT_CH
#define MAX_SLOTS 256

// Scratch (static __device__ allocation; runtime alloc forbidden)
__device__ float    g_proj[(size_t)N_NODES * F_TOT];   // 51.2 MB
__device__ float    g_norm[(size_t)N_NODES * HEADS];   // 1.6 MB
__device__ unsigned g_slot[HEADS * MAX_SLOTS];         // hashed per-head max slots
__device__ float    g_hmax[HEADS];                     // final per-head max

// monotone float->uint map (order-preserving); inverse for readback
__device__ __forceinline__ unsigned fmap(float f) {
    unsigned u = __float_as_uint(f);
    return (u & 0x80000000u) ? ~u : (u | 0x80000000u);
}
__device__ __forceinline__ float funmap(unsigned u) {
    return __uint_as_float((u & 0x80000000u) ? (u & 0x7FFFFFFFu) : ~u);
}

// fast tanh: 2 MUFU + few FMA; rel err ~1e-6 (validated: pipeline rel_err 3.7e-7)
__device__ __forceinline__ float fast_tanh(float x) {
    float ax = fabsf(x);
    float e  = __expf(2.0f * ax);             // inf for large ax -> r = 1
    float r  = 1.0f - __fdividef(2.0f, e + 1.0f);
    return copysignf(r, x);
}

// packed f32x2 helpers (sm_100+; .rn rounding identical to scalar FFMA)
#define PACK2(dst, lo, hi) \
    asm("mov.b64 %0, {%1, %2};" : "=l"(dst) : "f"(lo), "f"(hi))
#define BCAST2(dst, v) \
    asm("mov.b64 %0, {%1, %1};" : "=l"(dst) : "f"(v))
#define FMA2(acc, a, b) \
    asm("fma.rn.f32x2 %0, %1, %2, %0;" : "+l"(acc) : "l"(a), "l"(b))
#define UNPACK2(lo, hi, src) \
    asm("mov.b64 {%0, %1}, %2;" : "=f"(lo), "=f"(hi) : "l"(src))

// ---------------------------------------------------------------------------
// GEMM v4: 128x128 tile / 256 threads, 8x8 microtile computed with packed
// fma.rn.f32x2 (2 FMA lanes/instr): per k-step 32 FMA2 + 12 packs + 4 LDS.128
// instead of 64 FFMA + 4 LDS.128. Bit-identical rounding to scalar FFMA.
// Row pad 132 floats (16B-aligned rows).
// ---------------------------------------------------------------------------
__global__ __launch_bounds__(256) void gemm_kernel(const float* __restrict__ x,
                                                   const float* __restrict__ Wm) {
    __shared__ float xs_t[16][132];    // [k][row], pad 132 (16B-aligned rows)
    __shared__ float ws[16][128];      // [k][col]
    const int t  = threadIdx.x;
    const int tx = t & 15;             // col group
    const int ty = t >> 4;             // row group
    const int rowBase = blockIdx.x * 128;

    unsigned long long acc2[8][4];     // 8 rows x 4 col-pairs (f32x2)
#pragma unroll
    for (int i = 0; i < 8; i++)
#pragma unroll
        for (int j = 0; j < 4; j++) acc2[i][j] = 0ull;   // {0.f, 0.f}

    const int lr  = t >> 1;
    const int lk8 = (t & 1) * 8;
    int gr = rowBase + lr;
    if (gr >= N_NODES) gr = N_NODES - 1;   // clamp (dup loads OK, stores guarded)

    for (int kk = 0; kk < IN_CH; kk += 16) {
        float4 v0 = *(const float4*)(x + (size_t)gr * IN_CH + kk + lk8);
        float4 v1 = *(const float4*)(x + (size_t)gr * IN_CH + kk + lk8 + 4);
        xs_t[lk8 + 0][lr] = v0.x; xs_t[lk8 + 1][lr] = v0.y;
        xs_t[lk8 + 2][lr] = v0.z; xs_t[lk8 + 3][lr] = v0.w;
        xs_t[lk8 + 4][lr] = v1.x; xs_t[lk8 + 5][lr] = v1.y;
        xs_t[lk8 + 6][lr] = v1.z; xs_t[lk8 + 7][lr] = v1.w;
#pragma unroll
        for (int rep = 0; rep < 2; rep++) {
            int idx = t * 2 + rep;            // 0..511
            int k   = idx >> 5;               // 0..15
            int c4  = (idx & 31) * 4;         // 0..124
            *(float4*)&ws[k][c4] =
                *(const float4*)(Wm + (size_t)(kk + k) * F_TOT + c4);
        }
        __syncthreads();
#pragma unroll
        for (int k = 0; k < 16; k++) {
            float4 a0 = *(float4*)&xs_t[k][ty * 8];
            float4 a1 = *(float4*)&xs_t[k][ty * 8 + 4];
            float4 b0 = *(float4*)&ws[k][tx * 8];
            float4 b1 = *(float4*)&ws[k][tx * 8 + 4];
            unsigned long long bp[4];
            PACK2(bp[0], b0.x, b0.y);
            PACK2(bp[1], b0.z, b0.w);
            PACK2(bp[2], b1.x, b1.y);
            PACK2(bp[3], b1.z, b1.w);
            float a[8] = {a0.x, a0.y, a0.z, a0.w, a1.x, a1.y, a1.z, a1.w};
#pragma unroll
            for (int i = 0; i < 8; i++) {
                unsigned long long ab;
                BCAST2(ab, a[i]);
#pragma unroll
                for (int j = 0; j < 4; j++)
                    FMA2(acc2[i][j], ab, bp[j]);
            }
        }
        __syncthreads();
    }

#pragma unroll
    for (int i = 0; i < 8; i++) {
        int r = rowBase + ty * 8 + i;
        if (r < N_NODES) {
            float4 o0, o1;
            UNPACK2(o0.x, o0.y, acc2[i][0]);
            UNPACK2(o0.z, o0.w, acc2[i][1]);
            UNPACK2(o1.x, o1.y, acc2[i][2]);
            UNPACK2(o1.z, o1.w, acc2[i][3]);
            *(float4*)(g_proj + (size_t)r * F_TOT + tx * 8)     = o0;
            *(float4*)(g_proj + (size_t)r * F_TOT + tx * 8 + 4) = o1;
        }
    }
}

// ---------------------------------------------------------------------------
// Edge kernel (R11 known-good, verbatim): one warp per edge, 8 edges/block,
// E/8 = 200000 blocks exactly. Lane L owns channels [4L,4L+4), head = L>>3.
// ---------------------------------------------------------------------------
__global__ __launch_bounds__(256) void edge_kernel(const int* __restrict__ ei,
                                                   const float* __restrict__ att,
                                                   float* __restrict__ out) {
    const int warpInBlk = threadIdx.x >> 5;
    const int lane      = threadIdx.x & 31;
    const int edge      = blockIdx.x * 8 + warpInBlk;

    __shared__ float smax[8][HEADS];

    const int row = __ldg(ei + edge);
    const int col = __ldg(ei + N_EDGES + edge);

    const float4 s4 = *(const float4*)(g_proj + (size_t)row * F_TOT + lane * 4);
    const float4 d4 = *(const float4*)(g_proj + (size_t)col * F_TOT + lane * 4);
    const float4 a4 = *(const float4*)(att + lane * 4);

    float p = fast_tanh(s4.x + d4.x) * a4.x
            + fast_tanh(s4.y + d4.y) * a4.y
            + fast_tanh(s4.z + d4.z) * a4.z
            + fast_tanh(s4.w + d4.w) * a4.w;

    // reduce within each 8-lane head group (all lanes get the sum)
    p += __shfl_xor_sync(0xffffffffu, p, 4);
    p += __shfl_xor_sync(0xffffffffu, p, 2);
    p += __shfl_xor_sync(0xffffffffu, p, 1);

    if ((lane & 7) == 0) smax[warpInBlk][lane >> 3] = p;

    const float w = __expf(p);

    float* op = out + (size_t)col * F_TOT + lane * 4;
    asm volatile("red.global.add.v4.f32 [%0], {%1,%2,%3,%4};"
                 :: "l"(op), "f"(s4.x * w), "f"(s4.y * w),
                    "f"(s4.z * w), "f"(s4.w * w)
                 : "memory");

    if ((lane & 7) == 0)
        atomicAdd(g_norm + (size_t)col * HEADS + (lane >> 3), w);

    __syncthreads();
    if (threadIdx.x < HEADS) {
        float m = smax[0][threadIdx.x];
#pragma unroll
        for (int wb = 1; wb < 8; wb++) m = fmaxf(m, smax[wb][threadIdx.x]);
        atomicMax(&g_slot[threadIdx.x * MAX_SLOTS + (blockIdx.x & (MAX_SLOTS - 1))],
                  fmap(m));
    }
}

// ---------------------------------------------------------------------------
// Reduce hashed max slots -> g_hmax[h]
// ---------------------------------------------------------------------------
__global__ __launch_bounds__(256) void maxreduce_kernel() {
    __shared__ unsigned sm[256];
    const int t = threadIdx.x;
    for (int h = 0; h < HEADS; h++) {
        sm[t] = g_slot[h * MAX_SLOTS + t];
        __syncthreads();
        for (int s = 128; s > 0; s >>= 1) {
            if (t < s) sm[t] = max(sm[t], sm[t + s]);
            __syncthreads();
        }
        if (t == 0) g_hmax[h] = funmap(sm[0]);
        __syncthreads();
    }
}

// ---------------------------------------------------------------------------
// Finalize: exact reference semantics including the 1e-12 clamp:
//   scale = exp(-max_h); out = out_acc*scale / max(norm_acc*scale, 1e-12)
// ---------------------------------------------------------------------------
__global__ __launch_bounds__(256) void finalize_kernel(float* __restrict__ out) {
    size_t i4 = (size_t)blockIdx.x * blockDim.x + threadIdx.x;
    if (i4 >= (size_t)N_NODES * (F_TOT / 4)) return;
    int n = (int)(i4 >> 5);
    int q = (int)(i4 & 31);
    int h = q >> 3;
    float scale = __expf(-g_hmax[h]);
    float nr    = g_norm[(size_t)n * HEADS + h] * scale;
    float inv   = scale / fmaxf(nr, 1e-12f);
    float4 v = *(float4*)(out + i4 * 4);
    v.x *= inv; v.y *= inv; v.z *= inv; v.w *= inv;
    *(float4*)(out + i4 * 4) = v;
}

// ---------------------------------------------------------------------------
extern "C" void kernel_launch(void* const* d_in, const int* in_sizes, int n_in,
                              void* d_out, int out_size) {
    const float* x   = (const float*)d_in[0];
    const int*   ei  = (const int*)d_in[1];    // int32 edge_index [2, E]
    const float* Wm  = (const float*)d_in[2];
    const float* att = (const float*)d_in[3];
    float*       out = (float*)d_out;

    void* normPtr = nullptr;
    void* slotPtr = nullptr;
    cudaGetSymbolAddress(&normPtr, g_norm);
    cudaGetSymbolAddress(&slotPtr, g_slot);

    cudaMemsetAsync(out, 0, (size_t)N_NODES * F_TOT * sizeof(float));
    cudaMemsetAsync(normPtr, 0, (size_t)N_NODES * HEADS * sizeof(float));
    cudaMemsetAsync(slotPtr, 0, HEADS * MAX_SLOTS * sizeof(unsigned));

    gemm_kernel<<<(N_NODES + 127) / 128, 256>>>(x, Wm);

    edge_kernel<<<N_EDGES / 8, 256>>>(ei, att, out);   // 200000 blocks exactly

    maxreduce_kernel<<<1, 256>>>();

    const long long finElems = (long long)N_NODES * (F_TOT / 4);
    finalize_kernel<<<(unsigned)((finElems + 255) / 256), 256>>>(out);
}